// round 16
// baseline (speedup 1.0000x reference)
#include <cuda_runtime.h>
#include <cfloat>

#define POOL 7
#define SCALE 0.0625f
#define BATCH 4
#define CHANS 256
#define FH 224
#define FW 224
#define FHW (FH * FW)
#define N_ROIS 512
#define ROWSTR ((size_t)FW * CHANS)   // floats per feature row in NHWC

// Channel-last scratch: [b][h][w][c], 4*224*224*256 floats = 205.5 MB
__device__ float g_T[(size_t)BATCH * FHW * CHANS];

// Replicate XLA-GPU's fp32 division (approximate, NOT correctly rounded).
// This exact op is what makes rel_err == 0 vs the reference. DO NOT CHANGE.
__device__ __forceinline__ float div_full(float a, float b) {
    float r; asm("div.full.f32 %0, %1, %2;" : "=f"(r) : "f"(a), "f"(b)); return r;
}
// round_half_up(v * 0.0625) — exact in fp32 for the input range
__device__ __forceinline__ int rhus(float v) {
    return (int)floorf(__fadd_rn(__fmul_rn(v, SCALE), 0.5f));
}
__device__ __forceinline__ float4 fmax4(float4 a, float4 b) {
    return make_float4(fmaxf(a.x, b.x), fmaxf(a.y, b.y),
                       fmaxf(a.z, b.z), fmaxf(a.w, b.w));
}

// ---------------- Kernel 1: NCHW -> NHWC transpose (exact copy) ----------
__global__ void __launch_bounds__(256) transpose_kernel(const float* __restrict__ feat) {
    __shared__ float tile[32][33];
    const int b   = blockIdx.z;
    const int hw0 = blockIdx.x << 5;
    const int c0  = blockIdx.y << 5;
    const int tx = threadIdx.x, ty = threadIdx.y;   // (32,8)

    const float* src = feat + (size_t)b * CHANS * FHW;
    #pragma unroll
    for (int j = 0; j < 4; ++j)
        tile[ty + 8 * j][tx] = src[(size_t)(c0 + ty + 8 * j) * FHW + hw0 + tx];
    __syncthreads();
    float* dst = g_T + (size_t)b * FHW * CHANS;
    #pragma unroll
    for (int j = 0; j < 4; ++j)
        dst[(size_t)(hw0 + ty + 8 * j) * CHANS + c0 + tx] = tile[tx][ty + 8 * j];
}

// ---------------- Kernel 2: channel-last ROI max-pool ---------------------
// block = (roi n, chunk*8 + binGroup), 4 warps. Warp handles bins slot,
// slot+32 (49 bins over 32 slots). All 32 lanes cover one pixel's 128-ch
// chunk (512B): no half-split, no shuffles. Mainloop: 4-row x 2-col unroll
// = 8 independent LDG.128 in flight per warp.
__global__ void __launch_bounds__(128, 8) roipool_cl_kernel(
    const float* __restrict__ rois,
    float* __restrict__ out)
{
    const int warp = threadIdx.x >> 5;
    const int lane = threadIdx.x & 31;
    const int n     = blockIdx.x;
    const int chunk = blockIdx.y >> 3;           // 0..1 (slowest -> L2 phasing)
    const int bg    = blockIdx.y & 7;            // 0..7
    const int slot  = (bg << 2) + warp;          // 0..31
    const int c0    = chunk << 7;                // 128-channel chunk

    const float* roi = rois + n * 5;
    const int b  = (int)roi[0];
    const int xs = rhus(roi[1]);
    const int ys = rhus(roi[2]);
    const int xe = rhus(roi[3]);
    const int ye = rhus(roi[4]);
    const int roi_w = max(xe - xs + 1, 1);
    const int roi_h = max(ye - ys + 1, 1);
    const float bin_h = div_full((float)roi_h, 7.0f);
    const float bin_w = div_full((float)roi_w, 7.0f);

    const float* base = g_T + (size_t)b * FHW * CHANS + c0 + (lane << 2);
    const float NEG = -FLT_MAX;

    for (int bin = slot; bin < POOL * POOL; bin += 32) {
        const int ph = bin / POOL;
        const int pw = bin - ph * POOL;

        // Exact reference bin bounds (div.full + IEEE mul + floor/ceil + clip)
        const int hs = min(max((int)floorf(__fmul_rn((float)ph,       bin_h)) + ys, 0), FH);
        const int he = min(max((int)ceilf (__fmul_rn((float)(ph + 1), bin_h)) + ys, 0), FH);
        const int ws = min(max((int)floorf(__fmul_rn((float)pw,       bin_w)) + xs, 0), FW);
        const int we = min(max((int)ceilf (__fmul_rn((float)(pw + 1), bin_w)) + xs, 0), FW);
        const bool valid = (hs < he) && (ws < we);   // warp-uniform

        float4 acc0 = make_float4(NEG, NEG, NEG, NEG);
        float4 acc1 = acc0, acc2 = acc0, acc3 = acc0;
        if (valid) {
            int h = hs;
            // 4-row block, 2-col unroll: 8 independent LDG.128 in flight
            for (; h + 3 < he; h += 4) {
                const float* p = base + (size_t)(h * FW + ws) * CHANS;
                int w = ws;
                for (; w + 1 < we; w += 2, p += 2 * CHANS) {
                    float4 t0 = __ldg((const float4*)p);
                    float4 t1 = __ldg((const float4*)(p + ROWSTR));
                    float4 t2 = __ldg((const float4*)(p + 2 * ROWSTR));
                    float4 t3 = __ldg((const float4*)(p + 3 * ROWSTR));
                    float4 u0 = __ldg((const float4*)(p + CHANS));
                    float4 u1 = __ldg((const float4*)(p + CHANS + ROWSTR));
                    float4 u2 = __ldg((const float4*)(p + CHANS + 2 * ROWSTR));
                    float4 u3 = __ldg((const float4*)(p + CHANS + 3 * ROWSTR));
                    acc0 = fmax4(fmax4(acc0, t0), u0);
                    acc1 = fmax4(fmax4(acc1, t1), u1);
                    acc2 = fmax4(fmax4(acc2, t2), u2);
                    acc3 = fmax4(fmax4(acc3, t3), u3);
                }
                if (w < we) {
                    acc0 = fmax4(acc0, __ldg((const float4*)p));
                    acc1 = fmax4(acc1, __ldg((const float4*)(p + ROWSTR)));
                    acc2 = fmax4(acc2, __ldg((const float4*)(p + 2 * ROWSTR)));
                    acc3 = fmax4(acc3, __ldg((const float4*)(p + 3 * ROWSTR)));
                }
            }
            // 2-row tail
            for (; h + 1 < he; h += 2) {
                const float* p = base + (size_t)(h * FW + ws) * CHANS;
                int w = ws;
                for (; w + 1 < we; w += 2, p += 2 * CHANS) {
                    float4 t0 = __ldg((const float4*)p);
                    float4 t1 = __ldg((const float4*)(p + ROWSTR));
                    float4 u0 = __ldg((const float4*)(p + CHANS));
                    float4 u1 = __ldg((const float4*)(p + CHANS + ROWSTR));
                    acc0 = fmax4(fmax4(acc0, t0), u0);
                    acc1 = fmax4(fmax4(acc1, t1), u1);
                }
                if (w < we) {
                    acc0 = fmax4(acc0, __ldg((const float4*)p));
                    acc1 = fmax4(acc1, __ldg((const float4*)(p + ROWSTR)));
                }
            }
            // 1-row tail
            if (h < he) {
                const float* p = base + (size_t)(h * FW + ws) * CHANS;
                int w = ws;
                for (; w + 1 < we; w += 2, p += 2 * CHANS) {
                    float4 t0 = __ldg((const float4*)p);
                    float4 u0 = __ldg((const float4*)(p + CHANS));
                    acc2 = fmax4(fmax4(acc2, t0), u0);
                }
                if (w < we)
                    acc3 = fmax4(acc3, __ldg((const float4*)p));
            }
            acc0 = fmax4(fmax4(acc0, acc1), fmax4(acc2, acc3));
        } else {
            acc0 = make_float4(0.0f, 0.0f, 0.0f, 0.0f);
        }

        // out[n][c][ph][pw]; lane owns channels c0+4*lane..+3 (stride 49)
        const int oidx = (n * CHANS + c0 + (lane << 2)) * (POOL * POOL) + ph * POOL + pw;
        out[oidx]                   = acc0.x;
        out[oidx + POOL * POOL]     = acc0.y;
        out[oidx + 2 * POOL * POOL] = acc0.z;
        out[oidx + 3 * POOL * POOL] = acc0.w;
    }
}

extern "C" void kernel_launch(void* const* d_in, const int* in_sizes, int n_in,
                              void* d_out, int out_size) {
    const float* feat;
    const float* rois;
    if (in_sizes[0] > in_sizes[1]) {
        feat = (const float*)d_in[0];
        rois = (const float*)d_in[1];
    } else {
        feat = (const float*)d_in[1];
        rois = (const float*)d_in[0];
    }
    float* out = (float*)d_out;

    dim3 tgrid(FHW / 32, CHANS / 32, BATCH);     // 1568 x 8 x 4
    transpose_kernel<<<tgrid, dim3(32, 8)>>>(feat);

    dim3 pgrid(N_ROIS, 16);                      // 512 x (2 chunks * 8 bin-groups)
    roipool_cl_kernel<<<pgrid, 128>>>(rois, out);
}